// round 9
// baseline (speedup 1.0000x reference)
#include <cuda_runtime.h>

#define RR 256
#define TT 32
#define BB 32
#define YSZ 64

#define TILE 64
#define XS 68      // x tile with halo 2 on each side
#define HS 66      // conv1 output tile (halo 1 for conv2)
#define HSTR 68    // padded stride for 16B-aligned float4 loads
#define CH 4       // channels per hs pass

#define XS_FLOATS   (XS * XS)          // 4624
#define HS_FLOATS   (HS * HSTR)        // 4488
#define SMEM_FLOATS (XS_FLOATS + CH * HS_FLOATS + 288 + 288 + 32 + 1)
#define SMEM_BYTES  (SMEM_FLOATS * 4)  // 92740

// Packed fp32x2 ops (sm_103a): one issue slot = two fp32 FMAs.
#define FMA2(d, a, b, c) \
    asm("fma.rn.f32x2 %0, %1, %2, %3;" : "=l"(d) : "l"(a), "l"(b), "l"(c))
#define PACK2(d, lo, hi) \
    asm("mov.b64 %0, {%1, %2};" : "=l"(d) : "f"(lo), "f"(hi))
#define UNPACK2(lo, hi, s) \
    asm("mov.b64 {%0, %1}, %2;" : "=f"(lo), "=f"(hi) : "l"(s))

// 8MB scratch for stage-1 output (device global: no allocation)
__device__ float g_x[BB * RR * RR];

// ---------------------------------------------------------------------------
// Stage 1: x[b,p,q] = sum_t Ht[t,p,q] * yt[b,t,p>>2,q>>2]
// ---------------------------------------------------------------------------
__global__ __launch_bounds__(256) void stage1_kernel(
    const float* __restrict__ yt, const float* __restrict__ Ht)
{
    __shared__ float s_yt[4][TT][YSZ];   // 32 KB

    const int p   = blockIdx.x;
    const int bg  = blockIdx.y;
    const int tid = threadIdx.x;
    const int yr  = p >> 2;

    for (int i = tid; i < 4 * TT * YSZ; i += 256) {
        int q4 = i & 63;
        int t  = (i >> 6) & 31;
        int bl = i >> 11;
        s_yt[bl][t][q4] = yt[(((bg * 4 + bl) * TT + t) * YSZ + yr) * YSZ + q4];
    }
    __syncthreads();

    const int q  = tid;
    const int q4 = q >> 2;
    const float* hp = Ht + p * RR + q;

    float a0 = 0.f, a1 = 0.f, a2 = 0.f, a3 = 0.f;
#pragma unroll
    for (int t = 0; t < TT; t++) {
        float h = hp[t * RR * RR];
        a0 = fmaf(h, s_yt[0][t][q4], a0);
        a1 = fmaf(h, s_yt[1][t][q4], a1);
        a2 = fmaf(h, s_yt[2][t][q4], a2);
        a3 = fmaf(h, s_yt[3][t][q4], a3);
    }
    float* xp = g_x + (bg * 4) * RR * RR + p * RR + q;
    xp[0 * RR * RR] = a0;
    xp[1 * RR * RR] = a1;
    xp[2 * RR * RR] = a2;
    xp[3 * RR * RR] = a3;
}

// ---------------------------------------------------------------------------
// Conv(1->32,3x3) -> ReLU -> Conv(32->1,3x3), fused, CH=4 per pass.
// conv1: 726 six-row vertical mini-walks (3 LDS/point), channel-pair f32x2.
// conv2: packed f32x2 accumulators held across the whole kernel.
// Grid: (4, 4, 32). 256 threads. Dynamic smem 92.7 KB, 2 CTAs/SM.
// ---------------------------------------------------------------------------
__global__ __launch_bounds__(256, 2) void conv_fused_kernel(
    const float* __restrict__ W1, const float* __restrict__ b1,
    const float* __restrict__ W2, const float* __restrict__ b2,
    float* __restrict__ out)
{
    extern __shared__ float smem[];
    float* xs  = smem;                        // 68x68
    float* hsb = smem + XS_FLOATS;            // CH * 66x68
    float* w1s = hsb + CH * HS_FLOATS;        // 288
    float* w2s = w1s + 288;                   // 288
    float* b1s = w2s + 288;                   // 32
    float* b2s = b1s + 32;                    // 1

    const int b   = blockIdx.z;
    const int ty0 = blockIdx.y * TILE;
    const int tx0 = blockIdx.x * TILE;
    const int tid = threadIdx.x;

    for (int i = tid; i < 288; i += 256) { w1s[i] = W1[i]; w2s[i] = W2[i]; }
    if (tid < 32)  b1s[tid] = b1[tid];
    if (tid == 0)  b2s[0] = b2[0];

    // Load x tile with halo 2 (zero-pad at image borders)
    const float* xb = g_x + b * RR * RR;
    for (int i = tid; i < XS_FLOATS; i += 256) {
        int ry = i / XS, rx = i - ry * XS;
        int gy = ty0 - 2 + ry, gx = tx0 - 2 + rx;
        float v = 0.f;
        if (gy >= 0 && gy < RR && gx >= 0 && gx < RR) v = xb[gy * RR + gx];
        xs[i] = v;
    }
    __syncthreads();

    const int tx = tid & 15;
    const int ty = tid >> 4;
    const int ox = tx * 4;
    const int oy = ty * 4;

    // Packed accumulators: acc01[i] = (out[i][0], out[i][1]), acc23 = ([2],[3])
    unsigned long long acc01[4] = {0ull, 0ull, 0ull, 0ull};
    unsigned long long acc23[4] = {0ull, 0ull, 0ull, 0ull};

    for (int g = 0; g < 32 / CH; g++) {
        const int c0 = g * CH;

        // --- conv1 weights packed in channel pairs ---
        unsigned long long w1p0[9], w1p1[9], bcp0, bcp1;
#pragma unroll
        for (int k = 0; k < 9; k++) {
            PACK2(w1p0[k], w1s[(c0 + 0) * 9 + k], w1s[(c0 + 1) * 9 + k]);
            PACK2(w1p1[k], w1s[(c0 + 2) * 9 + k], w1s[(c0 + 3) * 9 + k]);
        }
        PACK2(bcp0, b1s[c0 + 0], b1s[c0 + 1]);
        PACK2(bcp1, b1s[c0 + 2], b1s[c0 + 3]);

        // --- conv1: 11 bands x 66 cols of 6-row vertical walks ---
        for (int s = tid; s < 11 * 66; s += 256) {
            int band = s / 66;
            int col  = s - band * 66;
            int r0   = band * 6;
            bool col_oob = ((unsigned)(tx0 + col - 1) >= RR);
            const float* xp = xs + r0 * XS + col;
            float* hp = hsb + r0 * HSTR + col;

            unsigned long long X0, X1, X2, X3, X4, X5, X6, X7, X8;
            float t0, t1, t2;
            t0 = xp[0];      t1 = xp[1];      t2 = xp[2];
            PACK2(X0, t0, t0); PACK2(X1, t1, t1); PACK2(X2, t2, t2);
            t0 = xp[XS];     t1 = xp[XS + 1]; t2 = xp[XS + 2];
            PACK2(X3, t0, t0); PACK2(X4, t1, t1); PACK2(X5, t2, t2);
            xp += 2 * XS;

            int gy = ty0 + r0 - 1;
#pragma unroll
            for (int r = 0; r < 6; r++) {
                t0 = xp[0]; t1 = xp[1]; t2 = xp[2];
                PACK2(X6, t0, t0); PACK2(X7, t1, t1); PACK2(X8, t2, t2);

                unsigned long long v0 = bcp0, v1 = bcp1;
                FMA2(v0, w1p0[0], X0, v0);  FMA2(v1, w1p1[0], X0, v1);
                FMA2(v0, w1p0[1], X1, v0);  FMA2(v1, w1p1[1], X1, v1);
                FMA2(v0, w1p0[2], X2, v0);  FMA2(v1, w1p1[2], X2, v1);
                FMA2(v0, w1p0[3], X3, v0);  FMA2(v1, w1p1[3], X3, v1);
                FMA2(v0, w1p0[4], X4, v0);  FMA2(v1, w1p1[4], X4, v1);
                FMA2(v0, w1p0[5], X5, v0);  FMA2(v1, w1p1[5], X5, v1);
                FMA2(v0, w1p0[6], X6, v0);  FMA2(v1, w1p1[6], X6, v1);
                FMA2(v0, w1p0[7], X7, v0);  FMA2(v1, w1p1[7], X7, v1);
                FMA2(v0, w1p0[8], X8, v0);  FMA2(v1, w1p1[8], X8, v1);

                float ra, rb, rc, rd;
                UNPACK2(ra, rb, v0);
                UNPACK2(rc, rd, v1);
                bool oob = col_oob || ((unsigned)gy >= RR);
                ra = oob ? 0.f : fmaxf(ra, 0.f);
                rb = oob ? 0.f : fmaxf(rb, 0.f);
                rc = oob ? 0.f : fmaxf(rc, 0.f);
                rd = oob ? 0.f : fmaxf(rd, 0.f);
                hp[0 * HS_FLOATS] = ra;
                hp[1 * HS_FLOATS] = rb;
                hp[2 * HS_FLOATS] = rc;
                hp[3 * HS_FLOATS] = rd;

                hp += HSTR; xp += XS; gy++;
                X0 = X3; X1 = X4; X2 = X5;
                X3 = X6; X4 = X7; X5 = X8;
            }
        }
        __syncthreads();

        // --- conv2: packed j-pairs, CH channels ---
#pragma unroll
        for (int cc = 0; cc < CH; cc++) {
            unsigned long long wp[9];
#pragma unroll
            for (int k = 0; k < 9; k++) {
                float w = w2s[(c0 + cc) * 9 + k];
                PACK2(wp[k], w, w);
            }
            const float* hc = hsb + cc * HS_FLOATS;
#pragma unroll
            for (int pr = 0; pr < 6; pr++) {
                const float* hq = hc + (oy + pr) * HSTR + ox;
                float4 v4 = *(const float4*)hq;
                float2 v2 = *(const float2*)(hq + 4);
                unsigned long long P0, P1, P2, P3, P4;
                PACK2(P0, v4.x, v4.y);
                PACK2(P1, v4.y, v4.z);
                PACK2(P2, v4.z, v4.w);
                PACK2(P3, v4.w, v2.x);
                PACK2(P4, v2.x, v2.y);
#pragma unroll
                for (int i = 0; i < 4; i++) {
                    int dy = pr - i;
                    if (dy >= 0 && dy < 3) {
                        FMA2(acc01[i], wp[dy * 3 + 0], P0, acc01[i]);
                        FMA2(acc01[i], wp[dy * 3 + 1], P1, acc01[i]);
                        FMA2(acc01[i], wp[dy * 3 + 2], P2, acc01[i]);
                        FMA2(acc23[i], wp[dy * 3 + 0], P2, acc23[i]);
                        FMA2(acc23[i], wp[dy * 3 + 1], P3, acc23[i]);
                        FMA2(acc23[i], wp[dy * 3 + 2], P4, acc23[i]);
                    }
                }
            }
        }
        __syncthreads();   // protect hs before next group overwrites it
    }

    float bb = b2s[0];
#pragma unroll
    for (int i = 0; i < 4; i++) {
        float o0, o1, o2, o3;
        UNPACK2(o0, o1, acc01[i]);
        UNPACK2(o2, o3, acc23[i]);
        float4 o;
        o.x = o0 + bb;
        o.y = o1 + bb;
        o.z = o2 + bb;
        o.w = o3 + bb;
        *(float4*)(out + (size_t)(b * RR + ty0 + oy + i) * RR + tx0 + ox) = o;
    }
}

extern "C" void kernel_launch(void* const* d_in, const int* in_sizes, int n_in,
                              void* d_out, int out_size) {
    const float* yt = (const float*)d_in[0];
    const float* Ht = (const float*)d_in[1];
    const float* W1 = (const float*)d_in[2];
    const float* b1 = (const float*)d_in[3];
    const float* W2 = (const float*)d_in[4];
    const float* b2 = (const float*)d_in[5];
    float* out = (float*)d_out;

    // Immediate (non-stream) API: executes at call time, not captured.
    cudaFuncSetAttribute(conv_fused_kernel,
                         cudaFuncAttributeMaxDynamicSharedMemorySize, SMEM_BYTES);

    stage1_kernel<<<dim3(256, 8), 256>>>(yt, Ht);
    conv_fused_kernel<<<dim3(4, 4, 32), 256, SMEM_BYTES>>>(W1, b1, W2, b2, out);
}

// round 10
// speedup vs baseline: 1.1641x; 1.1641x over previous
#include <cuda_runtime.h>

#define RR 256
#define TT 32
#define BB 32
#define YSZ 64

#define TILE 64
#define XS 68      // x tile with halo 2 on each side
#define HS 66      // conv1 output tile (halo 1 for conv2)
#define HSTR 68    // padded stride for 16B-aligned float4 loads
#define CH 4       // channels per hs pass

#define XS_FLOATS   (XS * XS)          // 4624
#define HS_FLOATS   (HS * HSTR)        // 4488
#define SMEM_FLOATS (XS_FLOATS + CH * HS_FLOATS + 288 + 288 + 32 + 1)
#define SMEM_BYTES  (SMEM_FLOATS * 4)  // 92740

// 8MB scratch for stage-1 output (device global: no allocation)
__device__ float g_x[BB * RR * RR];

// ---------------------------------------------------------------------------
// Stage 1: x[b,p,q] = sum_t Ht[t,p,q] * yt[b,t,p>>2,q>>2]
// ---------------------------------------------------------------------------
__global__ __launch_bounds__(256) void stage1_kernel(
    const float* __restrict__ yt, const float* __restrict__ Ht)
{
    __shared__ float s_yt[4][TT][YSZ];   // 32 KB

    const int p   = blockIdx.x;
    const int bg  = blockIdx.y;
    const int tid = threadIdx.x;
    const int yr  = p >> 2;

    for (int i = tid; i < 4 * TT * YSZ; i += 256) {
        int q4 = i & 63;
        int t  = (i >> 6) & 31;
        int bl = i >> 11;
        s_yt[bl][t][q4] = yt[(((bg * 4 + bl) * TT + t) * YSZ + yr) * YSZ + q4];
    }
    __syncthreads();

    const int q  = tid;
    const int q4 = q >> 2;
    const float* hp = Ht + p * RR + q;

    float a0 = 0.f, a1 = 0.f, a2 = 0.f, a3 = 0.f;
#pragma unroll
    for (int t = 0; t < TT; t++) {
        float h = hp[t * RR * RR];
        a0 = fmaf(h, s_yt[0][t][q4], a0);
        a1 = fmaf(h, s_yt[1][t][q4], a1);
        a2 = fmaf(h, s_yt[2][t][q4], a2);
        a3 = fmaf(h, s_yt[3][t][q4], a3);
    }
    float* xp = g_x + (bg * 4) * RR * RR + p * RR + q;
    xp[0 * RR * RR] = a0;
    xp[1 * RR * RR] = a1;
    xp[2 * RR * RR] = a2;
    xp[3 * RR * RR] = a3;
}

// ---------------------------------------------------------------------------
// Conv(1->32,3x3) -> ReLU -> Conv(32->1,3x3), fused, CH=4 per pass.
// conv1: scalar sliding-window vertical walks — 3 LDS per point, taps shifted
//        through registers (R8's L1 cut WITHOUT its f32x2/pack ALU cost).
// conv2: scalar 4x4 register tile (R7 form — fastest measured).
// Grid: (4, 4, 32). 256 threads. Dynamic smem 92.7 KB, 2 CTAs/SM.
// ---------------------------------------------------------------------------
__global__ __launch_bounds__(256, 2) void conv_fused_kernel(
    const float* __restrict__ W1, const float* __restrict__ b1,
    const float* __restrict__ W2, const float* __restrict__ b2,
    float* __restrict__ out)
{
    extern __shared__ float smem[];
    float* xs  = smem;                        // 68x68
    float* hsb = smem + XS_FLOATS;            // CH * 66x68
    float* w1s = hsb + CH * HS_FLOATS;        // 288
    float* w2s = w1s + 288;                   // 288
    float* b1s = w2s + 288;                   // 32
    float* b2s = b1s + 32;                    // 1

    const int b   = blockIdx.z;
    const int ty0 = blockIdx.y * TILE;
    const int tx0 = blockIdx.x * TILE;
    const int tid = threadIdx.x;

    for (int i = tid; i < 288; i += 256) { w1s[i] = W1[i]; w2s[i] = W2[i]; }
    if (tid < 32)  b1s[tid] = b1[tid];
    if (tid == 0)  b2s[0] = b2[0];

    // Load x tile with halo 2 (zero-pad at image borders)
    const float* xb = g_x + b * RR * RR;
    for (int i = tid; i < XS_FLOATS; i += 256) {
        int ry = i / XS, rx = i - ry * XS;
        int gy = ty0 - 2 + ry, gx = tx0 - 2 + rx;
        float v = 0.f;
        if (gy >= 0 && gy < RR && gx >= 0 && gx < RR) v = xb[gy * RR + gx];
        xs[i] = v;
    }
    __syncthreads();

    const int tx = tid & 15;
    const int ty = tid >> 4;
    const int ox = tx * 4;
    const int oy = ty * 4;

    float acc[4][4];
#pragma unroll
    for (int i = 0; i < 4; i++)
#pragma unroll
        for (int j = 0; j < 4; j++) acc[i][j] = 0.f;

    for (int g = 0; g < 32 / CH; g++) {
        const int c0 = g * CH;

        // stage weights for this channel group into registers
        float w1r[CH][9], bcr[CH];
#pragma unroll
        for (int cc = 0; cc < CH; cc++) {
#pragma unroll
            for (int k = 0; k < 9; k++) w1r[cc][k] = w1s[(c0 + cc) * 9 + k];
            bcr[cc] = b1s[c0 + cc];
        }

        // --- conv1: 11 bands x 66 cols of 6-row vertical sliding walks ---
        for (int s = tid; s < 11 * 66; s += 256) {
            int band = s / 66;
            int col  = s - band * 66;
            int r0   = band * 6;
            bool col_oob = ((unsigned)(tx0 + col - 1) >= RR);
            const float* xp = xs + r0 * XS + col;
            float* hp = hsb + r0 * HSTR + col;

            float x0 = xp[0],  x1 = xp[1],      x2 = xp[2];
            float x3 = xp[XS], x4 = xp[XS + 1], x5 = xp[XS + 2];
            xp += 2 * XS;

            int gy = ty0 + r0 - 1;
#pragma unroll
            for (int r = 0; r < 6; r++) {
                float x6 = xp[0], x7 = xp[1], x8 = xp[2];
                bool oob = col_oob || ((unsigned)gy >= RR);
#pragma unroll
                for (int cc = 0; cc < CH; cc++) {
                    float v = bcr[cc];
                    v = fmaf(w1r[cc][0], x0, v);
                    v = fmaf(w1r[cc][1], x1, v);
                    v = fmaf(w1r[cc][2], x2, v);
                    v = fmaf(w1r[cc][3], x3, v);
                    v = fmaf(w1r[cc][4], x4, v);
                    v = fmaf(w1r[cc][5], x5, v);
                    v = fmaf(w1r[cc][6], x6, v);
                    v = fmaf(w1r[cc][7], x7, v);
                    v = fmaf(w1r[cc][8], x8, v);
                    float rr = fmaxf(v, 0.f);
                    if (oob) rr = 0.f;
                    hp[cc * HS_FLOATS] = rr;
                }
                hp += HSTR; xp += XS; gy++;
                x0 = x3; x1 = x4; x2 = x5;
                x3 = x6; x4 = x7; x5 = x8;
            }
        }
        __syncthreads();

        // --- conv2: accumulate CH channels into 4x4 register tile (scalar) ---
#pragma unroll
        for (int cc = 0; cc < CH; cc++) {
            float w2r[9];
#pragma unroll
            for (int k = 0; k < 9; k++) w2r[k] = w2s[(c0 + cc) * 9 + k];
            const float* hc = hsb + cc * HS_FLOATS;
#pragma unroll
            for (int pr = 0; pr < 6; pr++) {
                const float* hq = hc + (oy + pr) * HSTR + ox;
                float4 v4 = *(const float4*)hq;
                float2 v2 = *(const float2*)(hq + 4);
                float rv[6] = { v4.x, v4.y, v4.z, v4.w, v2.x, v2.y };
#pragma unroll
                for (int i = 0; i < 4; i++) {
                    int dy = pr - i;
                    if (dy >= 0 && dy < 3) {
#pragma unroll
                        for (int j = 0; j < 4; j++) {
                            acc[i][j] = fmaf(w2r[dy * 3 + 0], rv[j],     acc[i][j]);
                            acc[i][j] = fmaf(w2r[dy * 3 + 1], rv[j + 1], acc[i][j]);
                            acc[i][j] = fmaf(w2r[dy * 3 + 2], rv[j + 2], acc[i][j]);
                        }
                    }
                }
            }
        }
        __syncthreads();   // protect hs before next group overwrites it
    }

    float bb = b2s[0];
#pragma unroll
    for (int i = 0; i < 4; i++) {
        float4 o;
        o.x = acc[i][0] + bb;
        o.y = acc[i][1] + bb;
        o.z = acc[i][2] + bb;
        o.w = acc[i][3] + bb;
        *(float4*)(out + (size_t)(b * RR + ty0 + oy + i) * RR + tx0 + ox) = o;
    }
}

extern "C" void kernel_launch(void* const* d_in, const int* in_sizes, int n_in,
                              void* d_out, int out_size) {
    const float* yt = (const float*)d_in[0];
    const float* Ht = (const float*)d_in[1];
    const float* W1 = (const float*)d_in[2];
    const float* b1 = (const float*)d_in[3];
    const float* W2 = (const float*)d_in[4];
    const float* b2 = (const float*)d_in[5];
    float* out = (float*)d_out;

    // Immediate (non-stream) API: executes at call time, not captured.
    cudaFuncSetAttribute(conv_fused_kernel,
                         cudaFuncAttributeMaxDynamicSharedMemorySize, SMEM_BYTES);

    stage1_kernel<<<dim3(256, 8), 256>>>(yt, Ht);
    conv_fused_kernel<<<dim3(4, 4, 32), 256, SMEM_BYTES>>>(W1, b1, W2, b2, out);
}